// round 1
// baseline (speedup 1.0000x reference)
#include <cuda_runtime.h>
#include <cuda_bf16.h>

// Problem constants (fixed by the dataset)
#define B_   2
#define T_   2048
#define DM   1024
#define H_   16
#define HD   64
#define ROWS (B_ * T_)        // 4096

// ---------------- scratch (no cudaMalloc allowed) ----------------
__device__ float g_q[B_ * T_ * DM];
__device__ float g_k[B_ * T_ * DM];
__device__ float g_v[B_ * T_ * DM];
__device__ float g_att[B_ * T_ * DM];

// =================================================================
// SGEMM: C[M,N] = A[M,K] @ B[N,K]^T   (both row-major, K contiguous)
// 128x128 tile, BK=8, 256 threads, 8x8 per thread, register prefetch.
// =================================================================
#define BM 128
#define BN 128
#define BK 8

__global__ void __launch_bounds__(256)
sgemm_abt(const float* __restrict__ A, const float* __restrict__ Bm,
          float* __restrict__ C, int M, int N, int K)
{
    __shared__ float As[BK][BM];
    __shared__ float Bs[BK][BN];

    const int bm = blockIdx.y;
    const int bn = blockIdx.x;
    const int tid = threadIdx.x;
    const int tx = tid & 15;        // 0..15  -> col group
    const int ty = tid >> 4;        // 0..15  -> row group

    // loader mapping: each thread loads one float4 of A-tile and one of B-tile
    const int arow = tid >> 1;             // 0..127
    const int acol = (tid & 1) * 4;        // 0 or 4
    const float* Ag = A + (size_t)(bm * BM + arow) * K + acol;
    const float* Bg = Bm + (size_t)(bn * BN + arow) * K + acol;

    float acc[8][8];
#pragma unroll
    for (int i = 0; i < 8; i++)
#pragma unroll
        for (int j = 0; j < 8; j++) acc[i][j] = 0.f;

    float4 a4 = *(const float4*)(Ag);
    float4 b4 = *(const float4*)(Bg);

    for (int k0 = 0; k0 < K; k0 += BK) {
        __syncthreads();
        As[acol + 0][arow] = a4.x;
        As[acol + 1][arow] = a4.y;
        As[acol + 2][arow] = a4.z;
        As[acol + 3][arow] = a4.w;
        Bs[acol + 0][arow] = b4.x;
        Bs[acol + 1][arow] = b4.y;
        Bs[acol + 2][arow] = b4.z;
        Bs[acol + 3][arow] = b4.w;
        __syncthreads();

        if (k0 + BK < K) {
            a4 = *(const float4*)(Ag + k0 + BK);
            b4 = *(const float4*)(Bg + k0 + BK);
        }

#pragma unroll
        for (int kk = 0; kk < BK; kk++) {
            float4 a0 = *(const float4*)&As[kk][ty * 8];
            float4 a1 = *(const float4*)&As[kk][ty * 8 + 4];
            float4 b0 = *(const float4*)&Bs[kk][tx * 8];
            float4 b1 = *(const float4*)&Bs[kk][tx * 8 + 4];
            float ar[8] = {a0.x, a0.y, a0.z, a0.w, a1.x, a1.y, a1.z, a1.w};
            float br[8] = {b0.x, b0.y, b0.z, b0.w, b1.x, b1.y, b1.z, b1.w};
#pragma unroll
            for (int i = 0; i < 8; i++)
#pragma unroll
                for (int j = 0; j < 8; j++)
                    acc[i][j] = fmaf(ar[i], br[j], acc[i][j]);
        }
    }

#pragma unroll
    for (int i = 0; i < 8; i++) {
        int row = bm * BM + ty * 8 + i;
        float* Cr = C + (size_t)row * N + bn * BN + tx * 8;
        float4 c0 = make_float4(acc[i][0], acc[i][1], acc[i][2], acc[i][3]);
        float4 c1 = make_float4(acc[i][4], acc[i][5], acc[i][6], acc[i][7]);
        *(float4*)Cr = c0;
        *(float4*)(Cr + 4) = c1;
    }
}

// =================================================================
// Flash attention with causal ALiBi.
// q,k,v,o layout: (B, T, H, HD) row-major  == the (B*T, 1024) GEMM layout.
// One thread per q row. K/V tiles of 32 rows staged in smem (broadcast LDS).
// =================================================================
#define AT_BM 128
#define AT_BN 32

__global__ void __launch_bounds__(AT_BM)
attn_kernel(const float* __restrict__ q, const float* __restrict__ k,
            const float* __restrict__ v, float* __restrict__ o)
{
    const int h = blockIdx.y;
    const int b = blockIdx.z;
    const int i0 = blockIdx.x * AT_BM;
    const int i = i0 + threadIdx.x;

    const float slope = exp2f(-8.0f * (float)(h + 1) / (float)H_);
    const float scale = 0.125f;  // 1/sqrt(64)

    __shared__ float ks[AT_BN][HD];
    __shared__ float vs[AT_BN][HD];

    // q row -> registers
    float4 qr[HD / 4];
    {
        const float4* qrow = (const float4*)(q + ((size_t)(b * T_ + i) * H_ + h) * HD);
#pragma unroll
        for (int d = 0; d < HD / 4; d++) qr[d] = qrow[d];
    }

    float4 oacc[HD / 4];
#pragma unroll
    for (int d = 0; d < HD / 4; d++) oacc[d] = make_float4(0.f, 0.f, 0.f, 0.f);
    float m = -1e30f, l = 0.f;

    const int kend = i0 + AT_BM;  // last key row needed by this CTA (exclusive)

    for (int kb0 = 0; kb0 < kend; kb0 += AT_BN) {
        __syncthreads();
        // stage K/V block: AT_BN x HD floats each; 128 threads x float4
        for (int idx = threadIdx.x; idx < AT_BN * (HD / 4); idx += AT_BM) {
            int r = idx / (HD / 4);
            int c = idx % (HD / 4);
            size_t base = ((size_t)(b * T_ + kb0 + r) * H_ + h) * HD;
            ((float4*)ks[r])[c] = ((const float4*)(k + base))[c];
            ((float4*)vs[r])[c] = ((const float4*)(v + base))[c];
        }
        __syncthreads();

        if (kb0 <= i) {
            float s[AT_BN];
            float bmax = m;
#pragma unroll
            for (int j = 0; j < AT_BN; j++) {
                const float4* kj = (const float4*)ks[j];
                float acc = 0.f;
#pragma unroll
                for (int d = 0; d < HD / 4; d++) {
                    float4 kd = kj[d];
                    acc = fmaf(qr[d].x, kd.x, acc);
                    acc = fmaf(qr[d].y, kd.y, acc);
                    acc = fmaf(qr[d].z, kd.z, acc);
                    acc = fmaf(qr[d].w, kd.w, acc);
                }
                int jj = kb0 + j;
                s[j] = (jj <= i) ? fmaf(-slope, (float)(i - jj), acc * scale)
                                 : -1e30f;
                bmax = fmaxf(bmax, s[j]);
            }
            float corr = __expf(m - bmax);
            m = bmax;
            l *= corr;
#pragma unroll
            for (int d = 0; d < HD / 4; d++) {
                oacc[d].x *= corr; oacc[d].y *= corr;
                oacc[d].z *= corr; oacc[d].w *= corr;
            }
#pragma unroll
            for (int j = 0; j < AT_BN; j++) {
                float p = __expf(s[j] - m);
                l += p;
                const float4* vj = (const float4*)vs[j];
#pragma unroll
                for (int d = 0; d < HD / 4; d++) {
                    float4 vd = vj[d];
                    oacc[d].x = fmaf(p, vd.x, oacc[d].x);
                    oacc[d].y = fmaf(p, vd.y, oacc[d].y);
                    oacc[d].z = fmaf(p, vd.z, oacc[d].z);
                    oacc[d].w = fmaf(p, vd.w, oacc[d].w);
                }
            }
        }
    }

    float inv = 1.f / l;
    float4* orow = (float4*)(o + ((size_t)(b * T_ + i) * H_ + h) * HD);
#pragma unroll
    for (int d = 0; d < HD / 4; d++) {
        float4 t = oacc[d];
        t.x *= inv; t.y *= inv; t.z *= inv; t.w *= inv;
        orow[d] = t;
    }
}

// =================================================================
extern "C" void kernel_launch(void* const* d_in, const int* in_sizes, int n_in,
                              void* d_out, int out_size)
{
    const float* x  = (const float*)d_in[0];
    const float* Wq = (const float*)d_in[1];
    const float* Wk = (const float*)d_in[2];
    const float* Wv = (const float*)d_in[3];
    const float* Wo = (const float*)d_in[4];
    float* out = (float*)d_out;

    float *q, *k, *v, *att;
    cudaGetSymbolAddress((void**)&q,   g_q);
    cudaGetSymbolAddress((void**)&k,   g_k);
    cudaGetSymbolAddress((void**)&v,   g_v);
    cudaGetSymbolAddress((void**)&att, g_att);

    dim3 gblock(256);
    dim3 ggrid(DM / BN, ROWS / BM);   // (8, 32)

    // Projections: y = x @ W^T, written in (B,T,H,HD)-compatible layout
    sgemm_abt<<<ggrid, gblock>>>(x, Wq, q, ROWS, DM, DM);
    sgemm_abt<<<ggrid, gblock>>>(x, Wk, k, ROWS, DM, DM);
    sgemm_abt<<<ggrid, gblock>>>(x, Wv, v, ROWS, DM, DM);

    // Attention
    dim3 agrid(T_ / AT_BM, H_, B_);   // (16, 16, 2)
    attn_kernel<<<agrid, AT_BM>>>(q, k, v, att);

    // Output projection
    sgemm_abt<<<ggrid, gblock>>>(att, Wo, out, ROWS, DM, DM);
}